// round 10
// baseline (speedup 1.0000x reference)
#include <cuda_runtime.h>
#include <cuda_bf16.h>
#include <cstdint>

#define NS 500000
#define EPS 1e-5f

// interleaved split-bf16 h: per site 64 u32 (32 hi-pairs then 32 lo-pairs)
__device__ __align__(16) unsigned g_h[NS * 64];
// ldmatrix images for W1 (k-major [K][N+8]) and W3 ([64][136])
__device__ __align__(16) unsigned short gW1hi[128 * 72], gW1lo[128 * 72];
__device__ __align__(16) unsigned short gW3hi[64 * 136], gW3lo[64 * 136];
// transposed W2 for direct-LDG B fragments: [9][64 n][64 k]
__device__ __align__(16) unsigned short gW2thi[9 * 64 * 64], gW2tlo[9 * 64 * 64];

__device__ __forceinline__ uint32_t s2u(const void* p) {
    uint32_t a;
    asm("{ .reg .u64 t; cvta.to.shared.u64 t, %1; cvt.u32.u64 %0, t; }" : "=r"(a) : "l"(p));
    return a;
}
__device__ __forceinline__ float silu(float x) { return x / (1.0f + __expf(-x)); }
// truncation split: hi = top 16 bits (exact), lo = rn(x - hi). 2 elements at once.
__device__ __forceinline__ void split2(float x0, float x1, unsigned& hi, unsigned& lo) {
    unsigned u0 = __float_as_uint(x0), u1 = __float_as_uint(x1);
    asm("prmt.b32 %0, %1, %2, 0x7632;" : "=r"(hi) : "r"(u0), "r"(u1));
    float l0 = x0 - __uint_as_float(u0 & 0xffff0000u);
    float l1 = x1 - __uint_as_float(u1 & 0xffff0000u);
    asm("cvt.rn.bf16x2.f32 %0, %1, %2;" : "=r"(lo) : "f"(l1), "f"(l0));
}
__device__ __forceinline__ void cpa16(uint32_t dst, const void* src) {
    asm volatile("cp.async.ca.shared.global [%0], [%1], 16;" :: "r"(dst), "l"(src));
}
#define CP_COMMIT() asm volatile("cp.async.commit_group;" ::: "memory")
#define CP_WAIT0()  asm volatile("cp.async.wait_group 0;" ::: "memory")
#define CP_WAIT1()  asm volatile("cp.async.wait_group 1;" ::: "memory")
__device__ __forceinline__ void ldmA(unsigned r[4], uint32_t a) {
    asm volatile("ldmatrix.sync.aligned.m8n8.x4.shared.b16 {%0,%1,%2,%3}, [%4];"
                 : "=r"(r[0]), "=r"(r[1]), "=r"(r[2]), "=r"(r[3]) : "r"(a));
}
__device__ __forceinline__ void ldmB(unsigned r[2], uint32_t a) {
    asm volatile("ldmatrix.sync.aligned.m8n8.x2.trans.shared.b16 {%0,%1}, [%2];"
                 : "=r"(r[0]), "=r"(r[1]) : "r"(a));
}
__device__ __forceinline__ void mmab(float d[4], const unsigned a[4], const unsigned b[2]) {
    asm volatile(
        "mma.sync.aligned.m16n8k16.row.col.f32.bf16.bf16.f32 "
        "{%0,%1,%2,%3},{%4,%5,%6,%7},{%8,%9},{%0,%1,%2,%3};"
        : "+f"(d[0]), "+f"(d[1]), "+f"(d[2]), "+f"(d[3])
        : "r"(a[0]), "r"(a[1]), "r"(a[2]), "r"(a[3]), "r"(b[0]), "r"(b[1]));
}

__global__ void kdum() {}

// ============================================================================
// k0: build weight images (W1/W3 ldmatrix images, W2 transposed for LDG frags)
// ============================================================================
__global__ void k0(const float* __restrict__ W1, const float* __restrict__ W2,
                   const float* __restrict__ W3) {
    int i = blockIdx.x * 256 + threadIdx.x;
    float x;
    unsigned short *dh, *dl;
    int idx;
    if (i < 9216) {                       // W1: [128k][64n] -> [128][72]
        int k = i / 72, n = i % 72;
        x = (n < 64) ? W1[k * 64 + n] : 0.f;
        idx = i; dh = gW1hi; dl = gW1lo;
    } else if (i < 46080) {               // W2t: [9][64 n][64 k] = W2[kk][k][n]
        int j = i - 9216;
        int kk = j >> 12, r = j & 4095, n = r >> 6, k = r & 63;
        x = W2[kk * 4096 + k * 64 + n];
        idx = j; dh = gW2thi; dl = gW2tlo;
    } else if (i < 54784) {               // W3: [64k][128n] -> [64][136]
        int j = i - 46080;
        int ki = j / 136, n = j % 136;
        x = (n < 128) ? W3[ki * 128 + n] : 0.f;
        idx = j; dh = gW3hi; dl = gW3lo;
    } else return;
    __nv_bfloat16 h = __float2bfloat16(x);
    dh[idx] = __bfloat16_as_ushort(h);
    dl[idx] = __bfloat16_as_ushort(__float2bfloat16(x - __bfloat162float(h)));
}

// ============================================================================
// k1: h = silu(bn1(feat @ W1))  [128 rows/block, 256 thr, warp = 16 rows]
// ============================================================================
#define O_B1HI 0
#define O_B1LO 18432
#define O_A1HI 36864
#define O_A1LO 47104
#define O_P1SC 57344
#define O_P1TB 57600
#define SM1    57856

__global__ __launch_bounds__(256, 3) void k1(
    const float* __restrict__ feat,
    const float* __restrict__ g1, const float* __restrict__ b1,
    const float* __restrict__ m1, const float* __restrict__ v1)
{
    extern __shared__ char sm[];
    uint32_t sb = s2u(sm);
    int t = threadIdx.x, wid = t >> 5, lane = t & 31;
    int base = blockIdx.x * 128;

    for (int q = t; q < 2304; q += 256) {
        if (q < 1152) cpa16(sb + O_B1HI + q * 16, gW1hi + q * 8);
        else          cpa16(sb + O_B1LO + (q - 1152) * 16, gW1lo + (q - 1152) * 8);
    }
    CP_COMMIT();
    if (t < 64) {
        float s = g1[t] * rsqrtf(v1[t] + EPS);
        ((float*)(sm + O_P1SC))[t] = s;
        ((float*)(sm + O_P1TB))[t] = b1[t] - m1[t] * s;
    }

    float d[8][4] = {};
    int arow = ((lane >> 3) & 1) * 8 + (lane & 7);
    int acol = (lane >> 4) * 16;
    int brow = arow;

    for (int kc = 0; kc < 4; kc++) {
        __syncthreads();
        #pragma unroll
        for (int i = 0; i < 4; i++) {
            int idx = t + 256 * i, r = idx >> 3, p = idx & 7;
            int site = base + r;
            float4 f = (site < NS) ? ((const float4*)feat)[(size_t)site * 32 + kc * 8 + p]
                                   : make_float4(0.f, 0.f, 0.f, 0.f);
            unsigned h0, l0, h1, l1;
            split2(f.x, f.y, h0, l0);
            split2(f.z, f.w, h1, l1);
            *(uint2*)(sm + O_A1HI + r * 80 + p * 8) = make_uint2(h0, h1);
            *(uint2*)(sm + O_A1LO + r * 80 + p * 8) = make_uint2(l0, l1);
        }
        CP_WAIT0();
        __syncthreads();
        unsigned ah[2][4], al[2][4];
        #pragma unroll
        for (int kq = 0; kq < 2; kq++) {
            uint32_t a = sb + O_A1HI + (wid * 16 + arow) * 80 + kq * 32 + acol;
            ldmA(ah[kq], a);
            ldmA(al[kq], a + (O_A1LO - O_A1HI));
        }
        #pragma unroll
        for (int n8 = 0; n8 < 8; n8++) {
            unsigned bh[2][2], bl[2][2];
            #pragma unroll
            for (int kq = 0; kq < 2; kq++) {
                uint32_t a = sb + O_B1HI + (kc * 32 + kq * 16 + brow) * 144 + n8 * 16;
                ldmB(bh[kq], a);
                ldmB(bl[kq], a + (O_B1LO - O_B1HI));
            }
            #pragma unroll
            for (int kq = 0; kq < 2; kq++) {
                mmab(d[n8], ah[kq], bh[kq]);
                mmab(d[n8], ah[kq], bl[kq]);
                mmab(d[n8], al[kq], bh[kq]);
            }
        }
    }
    const float* sc = (const float*)(sm + O_P1SC);
    const float* tb = (const float*)(sm + O_P1TB);
    #pragma unroll
    for (int n8 = 0; n8 < 8; n8++) {
        int c = 8 * n8 + 2 * (lane & 3);
        float s0 = sc[c], s1 = sc[c + 1], t0 = tb[c], t1 = tb[c + 1];
        #pragma unroll
        for (int h = 0; h < 2; h++) {
            int site = base + wid * 16 + (lane >> 2) + 8 * h;
            if (site < NS) {
                float o0 = silu(d[n8][2 * h] * s0 + t0);
                float o1 = silu(d[n8][2 * h + 1] * s1 + t1);
                unsigned hw, lw;
                split2(o0, o1, hw, lw);
                g_h[(size_t)site * 64 + (c >> 1)] = hw;
                g_h[(size_t)site * 64 + 32 + (c >> 1)] = lw;
            }
        }
    }
}

// ============================================================================
// k2: cv2 (pipelined gather, W2 B-frags via LDG from L2-hot W2t) + BN2/SiLU +
//     cv3 (2x4 warp tiling, hoisted B) + BN3 + residual + SiLU
// ============================================================================
#define O_ACC  0           // f32 [128][66] = 33792
#define O_LP   33792       // u32 [9][128]
#define O_CN   38400
#define O_IT   38448
#define O_NI   38528
#define O_SC2  38544
#define O_TB2  38800
#define O_SC3  39056
#define O_TB3  39568
#define O_G0   40096       // gather slot 0: hi[64*144] + lo[64*144]
#define O_G1   58528       // gather slot 1
#define SM2    76960
#define O_W3HI 0           // post-cv2: W3 image over ACC region
#define O_W3LO 17408
#define O_A3HI 40096       // A3 tile over gather slots
#define O_A3LO 58528

__global__ __launch_bounds__(256, 2) void k2(
    const float* __restrict__ feat, const int* __restrict__ nbr,
    const float* __restrict__ g2, const float* __restrict__ b2,
    const float* __restrict__ m2, const float* __restrict__ v2,
    const float* __restrict__ g3, const float* __restrict__ b3,
    const float* __restrict__ m3, const float* __restrict__ v3,
    float* __restrict__ out)
{
    extern __shared__ char sm[];
    uint32_t sb = s2u(sm);
    int t = threadIdx.x, wid = t >> 5, lane = t & 31;
    int base = blockIdx.x * 128;
    unsigned* lp = (unsigned*)(sm + O_LP);
    int* cnt9 = (int*)(sm + O_CN);
    int* items = (int*)(sm + O_IT);
    float* acc = (float*)(sm + O_ACC);

    if (t < 64) {
        float s = g2[t] * rsqrtf(v2[t] + EPS);
        ((float*)(sm + O_SC2))[t] = s;
        ((float*)(sm + O_TB2))[t] = b2[t] - m2[t] * s;
    }
    if (t < 128) {
        float s = g3[t] * rsqrtf(v3[t] + EPS);
        ((float*)(sm + O_SC3))[t] = s;
        ((float*)(sm + O_TB3))[t] = b3[t] - m3[t] * s;
    }
    #pragma unroll
    for (int i = 0; i < 33; i++) acc[t + 256 * i] = 0.f;

    // compaction: warp w handles offsets w, w+8
    for (int k = wid; k < 9; k += 8) {
        int cbase = 0;
        #pragma unroll
        for (int g = 0; g < 4; g++) {
            int site = base + g * 32 + lane;
            int id = (site < NS) ? __ldg(&nbr[(size_t)k * NS + site]) : NS;
            bool val = id < NS;
            unsigned msk = __ballot_sync(0xffffffffu, val);
            if (val) {
                int p = cbase + __popc(msk & ((1u << lane) - 1u));
                lp[k * 128 + p] = ((unsigned)id << 8) | (g * 32 + lane);
            }
            cbase += __popc(msk);
        }
        if (lane == 0) cnt9[k] = cbase;
    }
    __syncthreads();
    if (t == 0) {
        int ni = 0;
        for (int k = 0; k < 9; k++)
            for (int c0 = 0; c0 < cnt9[k]; c0 += 64)
                items[ni++] = (k << 1) | (c0 >> 6);
        *(int*)(sm + O_NI) = ni;
    }
    __syncthreads();
    int nitems = *(int*)(sm + O_NI);

    auto issue_item = [&](int j) {
        int pk = items[j];
        int kk = pk >> 1, c0 = (pk & 1) << 6;
        int chunk = min(cnt9[kk] - c0, 64);
        uint32_t gb = sb + ((j & 1) ? O_G1 : O_G0);
        for (int q = t; q < chunk * 16; q += 256) {
            int r = q >> 4, s = q & 15;
            unsigned id = lp[kk * 128 + c0 + r] >> 8;
            uint32_t dst = (s < 8) ? gb + r * 144 + s * 16
                                   : gb + 9216 + r * 144 + (s - 8) * 16;
            cpa16(dst, g_h + (size_t)id * 64 + s * 4);
        }
    };

    int arow = ((lane >> 3) & 1) * 8 + (lane & 7);
    int acol = (lane >> 4) * 16;
    int brow = arow;

    issue_item(0);
    CP_COMMIT();

    for (int it = 0; it < nitems; it++) {
        __syncthreads();
        if (it + 1 < nitems) issue_item(it + 1);
        CP_COMMIT();
        if (it + 1 < nitems) CP_WAIT1(); else CP_WAIT0();
        __syncthreads();

        int pk = items[it];
        int kk = pk >> 1, c0 = (pk & 1) << 6;
        int chunk = min(cnt9[kk] - c0, 64);
        uint32_t gb = sb + ((it & 1) ? O_G1 : O_G0);
        int mtiles = (chunk + 15) >> 4;

        // B fragments via LDG.32 from transposed L2-hot W2t (n = 8*wid + lane>>2)
        const unsigned short* wth = gW2thi + kk * 4096 + (8 * wid + (lane >> 2)) * 64 + (lane & 3) * 2;
        const unsigned short* wtl = gW2tlo + kk * 4096 + (8 * wid + (lane >> 2)) * 64 + (lane & 3) * 2;
        unsigned bhf[4][2], blf[4][2];
        #pragma unroll
        for (int kq = 0; kq < 4; kq++) {
            bhf[kq][0] = *(const unsigned*)(wth + kq * 16);
            bhf[kq][1] = *(const unsigned*)(wth + kq * 16 + 8);
            blf[kq][0] = *(const unsigned*)(wtl + kq * 16);
            blf[kq][1] = *(const unsigned*)(wtl + kq * 16 + 8);
        }
        for (int mt = 0; mt < mtiles; mt++) {
            unsigned ah[4][4], al[4][4];
            #pragma unroll
            for (int kq = 0; kq < 4; kq++) {
                uint32_t a = gb + (mt * 16 + arow) * 144 + kq * 32 + acol;
                ldmA(ah[kq], a);
                ldmA(al[kq], a + 9216);
            }
            float dd[4] = {};
            #pragma unroll
            for (int kq = 0; kq < 4; kq++) {
                mmab(dd, ah[kq], bhf[kq]);
                mmab(dd, ah[kq], blf[kq]);
                mmab(dd, al[kq], bhf[kq]);
            }
            int c = 8 * wid + 2 * (lane & 3);
            #pragma unroll
            for (int h = 0; h < 2; h++) {
                int gr = mt * 16 + (lane >> 2) + 8 * h;
                if (gr < chunk) {
                    int rw = lp[kk * 128 + c0 + gr] & 255;
                    float2* ap = (float2*)(acc + rw * 66 + c);
                    float2 v = *ap;
                    v.x += dd[2 * h]; v.y += dd[2 * h + 1];
                    *ap = v;
                }
            }
        }
    }
    __syncthreads();
    // BN2 + SiLU -> split bf16 A3 tile (into gather slots)
    const float* sc2 = (const float*)(sm + O_SC2);
    const float* tb2 = (const float*)(sm + O_TB2);
    #pragma unroll
    for (int i = 0; i < 16; i++) {
        int idx = t + 256 * i, r = idx >> 5, p = idx & 31;
        float x0 = acc[r * 66 + 2 * p] * sc2[2 * p] + tb2[2 * p];
        float x1 = acc[r * 66 + 2 * p + 1] * sc2[2 * p + 1] + tb2[2 * p + 1];
        x0 = silu(x0); x1 = silu(x1);
        unsigned hw, lw;
        split2(x0, x1, hw, lw);
        *(unsigned*)(sm + O_A3HI + r * 144 + p * 4) = hw;
        *(unsigned*)(sm + O_A3LO + r * 144 + p * 4) = lw;
    }
    __syncthreads();   // ACC reads done before W3 overwrites it
    for (int q = t; q < 2176; q += 256) {
        if (q < 1088) cpa16(sb + O_W3HI + q * 16, gW3hi + q * 8);
        else          cpa16(sb + O_W3LO + (q - 1088) * 16, gW3lo + (q - 1088) * 8);
    }
    CP_COMMIT();
    CP_WAIT0();
    __syncthreads();
    // cv3: warp = (rg row-half: 64 rows) x (cg col-group: 32 cols), hoisted B
    const float* sc3 = (const float*)(sm + O_SC3);
    const float* tb3 = (const float*)(sm + O_TB3);
    int cg = wid & 3, rg = wid >> 2;
    unsigned b_h[4][4][2], b_l[4][4][2];   // [n8][kq][2]
    #pragma unroll
    for (int n8 = 0; n8 < 4; n8++)
        #pragma unroll
        for (int kq = 0; kq < 4; kq++) {
            uint32_t a = sb + O_W3HI + (kq * 16 + brow) * 272 + cg * 64 + n8 * 16;
            ldmB(b_h[n8][kq], a);
            ldmB(b_l[n8][kq], a + (O_W3LO - O_W3HI));
        }
    for (int mt = 0; mt < 4; mt++) {
        unsigned ah[4][4], al[4][4];
        #pragma unroll
        for (int kq = 0; kq < 4; kq++) {
            uint32_t a = sb + O_A3HI + (rg * 64 + mt * 16 + arow) * 144 + kq * 32 + acol;
            ldmA(ah[kq], a);
            ldmA(al[kq], a + (O_A3LO - O_A3HI));
        }
        #pragma unroll
        for (int n8 = 0; n8 < 4; n8++) {
            float dd[4] = {};
            #pragma unroll
            for (int kq = 0; kq < 4; kq++) {
                mmab(dd, ah[kq], b_h[n8][kq]);
                mmab(dd, ah[kq], b_l[n8][kq]);
                mmab(dd, al[kq], b_h[n8][kq]);
            }
            int c = cg * 32 + n8 * 8 + 2 * (lane & 3);
            float s0 = sc3[c], s1 = sc3[c + 1], t0 = tb3[c], t1 = tb3[c + 1];
            #pragma unroll
            for (int h = 0; h < 2; h++) {
                int site = base + rg * 64 + mt * 16 + (lane >> 2) + 8 * h;
                if (site < NS) {
                    float2 f = *(const float2*)(feat + (size_t)site * 128 + c);
                    float o0 = silu(dd[2 * h] * s0 + t0 + f.x);
                    float o1 = silu(dd[2 * h + 1] * s1 + t1 + f.y);
                    *(float2*)(out + (size_t)site * 128 + c) = make_float2(o0, o1);
                }
            }
        }
    }
}

// ============================================================================
extern "C" void kernel_launch(void* const* d_in, const int* in_sizes, int n_in,
                              void* d_out, int out_size) {
    const float* feat = (const float*)d_in[0];
    const int*   nbr  = (const int*)d_in[1];
    const float* W1 = (const float*)d_in[2];
    const float* W2 = (const float*)d_in[3];
    const float* W3 = (const float*)d_in[4];
    const float* g1 = (const float*)d_in[5];
    const float* b1 = (const float*)d_in[6];
    const float* m1 = (const float*)d_in[7];
    const float* v1 = (const float*)d_in[8];
    const float* g2 = (const float*)d_in[9];
    const float* b2 = (const float*)d_in[10];
    const float* m2 = (const float*)d_in[11];
    const float* v2 = (const float*)d_in[12];
    const float* g3 = (const float*)d_in[13];
    const float* b3 = (const float*)d_in[14];
    const float* m3 = (const float*)d_in[15];
    const float* v3 = (const float*)d_in[16];
    float* out = (float*)d_out;

    cudaFuncSetAttribute(k1, cudaFuncAttributeMaxDynamicSharedMemorySize, SM1);
    cudaFuncSetAttribute(k2, cudaFuncAttributeMaxDynamicSharedMemorySize, SM2);

    int grid = (NS + 127) / 128;   // 3907
    kdum<<<1, 32>>>();
    k0<<<214, 256>>>(W1, W2, W3);
    k1<<<grid, 256, SM1>>>(feat, g1, b1, m1, v1);
    k2<<<grid, 256, SM2>>>(feat, nbr, g2, b2, m2, v2, g3, b3, m3, v3, out);
}